// round 5
// baseline (speedup 1.0000x reference)
#include <cuda_runtime.h>
#include <cstdint>

#define TT 2048
#define DD 512
#define STEPS 8
#define NBLK (TT / STEPS)   // 256
#define NSTG 3
#define TILE_R 32           // rows per CTA
#define STEP_F 128          // floats per step in a stage: r32 w32 k32 v32
#define STAGE_B (STEPS * STEP_F * 4)  // 4096 bytes per stage buffer
#define PPITCH 65           // part[] col pitch (floats): conflict-free R/W
#define NRB 16              // row blocks

// 16 row-blocks of partial y sums, [16][T][D] = 64 MB scratch
__device__ float g_part[(size_t)NRB * TT * DD];

typedef unsigned long long ull;

__device__ __forceinline__ ull pk2(float lo, float hi) {
    ull r; asm("mov.b64 %0,{%1,%2};" : "=l"(r) : "f"(lo), "f"(hi)); return r;
}
__device__ __forceinline__ void up2(ull x, float& lo, float& hi) {
    asm("mov.b64 {%0,%1},%2;" : "=f"(lo), "=f"(hi) : "l"(x));
}
__device__ __forceinline__ ull f2fma(ull a, ull b, ull c) {
    ull d; asm("fma.rn.f32x2 %0,%1,%2,%3;" : "=l"(d) : "l"(a), "l"(b), "l"(c)); return d;
}
__device__ __forceinline__ ull f2mul(ull a, ull b) {
    ull d; asm("mul.rn.f32x2 %0,%1,%2;" : "=l"(d) : "l"(a), "l"(b)); return d;
}

#define CP16(dst, src) asm volatile("cp.async.cg.shared.global [%0], [%1], 16;\n" :: "r"(dst), "l"(src))
#define CP_COMMIT()    asm volatile("cp.async.commit_group;\n")
#define CP_WAIT1()     asm volatile("cp.async.wait_group 1;\n" ::: "memory")

// ---------------------------------------------------------------------------
// Main recurrence kernel. Grid: (16 col-blocks, 16 row-blocks) = 256 CTAs,
// 2 CTAs/SM (16 warps/SM -> 4/SMSP for latency hiding).
// CTA tile: 32 rows x 32 cols. Warp wid owns cols [wid*4,wid*4+4), all 32
// rows; lane = rg*4 + c (rg 0..7 = 4-row groups). Thread: 4 rows x 1 col as
// 2 f32x2 pairs. One __syncthreads + one batched smem reduction per 8 steps.
// ---------------------------------------------------------------------------
__global__ void __launch_bounds__(256, 2) wkv_main(
    const float* __restrict__ r, const float* __restrict__ w,
    const float* __restrict__ k, const float* __restrict__ v,
    const float* __restrict__ init_state, float* __restrict__ state_out)
{
    __shared__ __align__(16) float stage[NSTG][STEPS][STEP_F];
    __shared__ float part[2][32 * PPITCH];   // [parity][col*65 + rg*8 + st]

    const int tid  = threadIdx.x;
    const int bx   = blockIdx.x;   // 0..15 col block
    const int by   = blockIdx.y;   // 0..15 row block
    const int wid  = tid >> 5;     // warp id (0..7) -> col group
    const int lane = tid & 31;
    const int c    = lane & 3;     // col within warp group
    const int rg   = lane >> 2;    // row group (0..7), 4 rows each
    const int col32 = wid * 4 + c;           // col within CTA tile
    const int b    = bx * 32 + col32;        // global column
    const int a0   = by * TILE_R + rg * 4;   // first global row

    // ---- cp.async roles: every thread loads ONE 16B piece for ONE step.
    // tid = sgrp*32 + role; sgrp = step within block (0..7), role = 0..31.
    const int sgrp = tid >> 5;
    const int role = tid & 31;
    const float* basep; int off;
    if (role < 24) {
        const int vec = role >> 3;                    // 0=r 1=w 2=k
        basep = ((vec == 0) ? r : (vec == 1) ? w : k) + by * TILE_R + (role & 7) * 4;
        off = vec * 32 + (role & 7) * 4;
    } else {
        const int q = role - 24;
        basep = v + bx * 32 + q * 4;
        off = 96 + q * 4;
    }
    const float* pA = basep + (size_t)sgrp * DD;
    const unsigned st0 = (unsigned)__cvta_generic_to_shared(&stage[0][0][0]);
    const unsigned offA = st0 + (unsigned)(sgrp * STEP_F + off) * 4u;

    // ---- init state: state0[a][b] = init_state[b]
    const float is0 = init_state[b];
    ull s2[2];
    {
        ull iv = pk2(is0, is0);
        s2[0] = iv; s2[1] = iv;
    }

    // ---- prologue: stage blocks 0 and 1
    CP16(offA, pA);                     CP_COMMIT();
    CP16(offA + STAGE_B, pA + STEPS * DD); CP_COMMIT();
    pA += 2 * STEPS * DD;
    CP_WAIT1();
    __syncthreads();

    // writer base: part[p] + col32*65 + rg*8 ; reader: (st=wid, col=lane)
    const int wbase = col32 * PPITCH + rg * 8;
    const int rbase = lane * PPITCH + wid;
    float* gpr = g_part + (size_t)by * TT * DD + (size_t)bx * 32 + lane;
    const int vidx = 96 + col32;

    int gOff  = 0;                 // byte offset of compute buffer
    unsigned giOff = 2 * STAGE_B;  // byte offset of next issue buffer

    for (int blk = 0; blk < NBLK; blk++) {
        const int p = blk & 1;
        const char* sgb = (const char*)stage + gOff;
        float vals[STEPS];

#pragma unroll
        for (int st = 0; st < STEPS; st++) {
            const ull* sb = (const ull*)(sgb + st * (STEP_F * 4));

            ulonglong2 ra = *reinterpret_cast<const ulonglong2*>(sb + rg * 2);
            ulonglong2 wa = *reinterpret_cast<const ulonglong2*>(sb + 16 + rg * 2);
            ulonglong2 ka = *reinterpret_cast<const ulonglong2*>(sb + 32 + rg * 2);
            const float vf = ((const float*)sb)[vidx];
            const ull vv = pk2(vf, vf);

            // y partial = sum over this thread's 4 rows of r[a]*state[a][b]
            ull p2;
            p2 = f2mul(ra.x, s2[0]);
            p2 = f2fma(ra.y, s2[1], p2);

            // state update: s = w*s + k*v
            s2[0] = f2fma(wa.x, s2[0], f2mul(ka.x, vv));
            s2[1] = f2fma(wa.y, s2[1], f2mul(ka.y, vv));

            float pl, ph; up2(p2, pl, ph);
            vals[st] = pl + ph;
        }

        // batched partial write: 8 STS.32, conflict-free (pitch 65)
        {
            float* pw = &part[p][wbase];
#pragma unroll
            for (int st = 0; st < STEPS; st++) pw[st] = vals[st];
        }

        // stage block blk+2 (1 CP16 per thread)
        if ((blk + 2) < NBLK) CP16(offA + giOff, pA);
        pA += STEPS * DD;
        CP_COMMIT();
        CP_WAIT1();
        __syncthreads();

        // batched reduction: thread (st=wid, col=lane) sums 8 row-group
        // partials; conflict-free reads, coalesced 128B g_part store.
        {
            const float* pr = &part[p][rbase];
            float acc = pr[0];
#pragma unroll
            for (int g = 1; g < 8; g++) acc += pr[g * 8];
            gpr[(size_t)(blk * STEPS + wid) * DD] = acc;
        }

        gOff  = (gOff  == (NSTG - 1) * STAGE_B) ? 0 : gOff  + STAGE_B;
        giOff = (giOff == (NSTG - 1) * STAGE_B) ? 0 : giOff + STAGE_B;
    }

    // ---- final state write (4 rows x 1 col per thread)
    if (state_out) {
#pragma unroll
        for (int i = 0; i < 2; i++) {
            float lo, hi; up2(s2[i], lo, hi);
            state_out[(size_t)(a0 + 2 * i)     * DD + b] = lo;
            state_out[(size_t)(a0 + 2 * i + 1) * DD + b] = hi;
        }
    }
}

// ---------------------------------------------------------------------------
// Combine: y[t][b] = (sum_a r*u*k)*v[t][b] + sum of 16 row-block partials.
// float2-vectorized: 256 threads cover 512 cols as 256 float2s.
// ---------------------------------------------------------------------------
__global__ void __launch_bounds__(256) wkv_combine(
    const float* __restrict__ r, const float* __restrict__ k,
    const float* __restrict__ u, const float* __restrict__ v,
    float* __restrict__ y)
{
    const int t = blockIdx.x;
    const int tid = threadIdx.x;
    __shared__ float red[8];

    const float* rt = r + (size_t)t * DD;
    const float* kt = k + (size_t)t * DD;

    float p = rt[tid] * u[tid] * kt[tid]
            + rt[tid + 256] * u[tid + 256] * kt[tid + 256];
#pragma unroll
    for (int m = 16; m >= 1; m >>= 1) p += __shfl_xor_sync(0xffffffffu, p, m);
    if ((tid & 31) == 0) red[tid >> 5] = p;
    __syncthreads();

    float ruk = 0.f;
#pragma unroll
    for (int g = 0; g < 8; g++) ruk += red[g];

    const float2* v2 = (const float2*)(v + (size_t)t * DD);
    float2* y2 = (float2*)(y + (size_t)t * DD);
    float2 vv = v2[tid];
    float2 acc; acc.x = ruk * vv.x; acc.y = ruk * vv.y;
#pragma unroll
    for (int g = 0; g < NRB; g++) {
        const float2* gp2 = (const float2*)(g_part + (size_t)g * TT * DD + (size_t)t * DD);
        float2 pv = gp2[tid];
        acc.x += pv.x; acc.y += pv.y;
    }
    y2[tid] = acc;
}

// ---------------------------------------------------------------------------
extern "C" void kernel_launch(void* const* d_in, const int* in_sizes, int n_in,
                              void* d_out, int out_size) {
    const float* r          = (const float*)d_in[0];
    const float* w          = (const float*)d_in[1];
    const float* k          = (const float*)d_in[2];
    const float* v          = (const float*)d_in[3];
    const float* init_state = (const float*)d_in[4];
    const float* u          = (const float*)d_in[5];
    float* out = (float*)d_out;

    const int NTD = TT * DD;   // 1048576
    const int NDD = DD * DD;   // 262144

    float* y  = nullptr;
    float* st = nullptr;
    if (out_size >= NTD) {
        y = out;
        if (out_size >= NTD + NDD) st = out + NTD;
    } else if (out_size == NDD) {
        st = out;
    }

    wkv_main<<<dim3(16, 16), 256>>>(r, w, k, v, init_state, st);
    if (y) wkv_combine<<<TT, 256>>>(r, k, u, v, y);
}